// round 2
// baseline (speedup 1.0000x reference)
#include <cuda_runtime.h>
#include <cuda_bf16.h>

#define NN 20000
#define EE 320000
#define ETOT 340000   // EE + NN self loops
#define NODD 512
#define HIDD 128
#define HEADS 4
#define NLAYERS 3

// ---------------- static scratch (no runtime allocation) ----------------
__device__ float d_h[NN * HIDD];            // node features (updated in place per layer)
__device__ float d_z[NN * HEADS * HIDD];    // per-layer projected features [N][H][D]
__device__ float d_es[NN * HEADS];          // e_src per node/head
__device__ float d_ed[NN * HEADS];          // e_dst per node/head
__device__ int   d_cnt[NN];
__device__ int   d_cur[NN];
__device__ int   d_off[NN + 1];
__device__ int   d_csr[ETOT];               // src node per incoming edge, grouped by dst
__device__ float d_P[NODD * HIDD];          // emb @ sW1[:128] + sb1
__device__ float d_Q[NODD * HIDD];          // emb @ sW1[128:]

// ---------------- 0: node projection h = relu(x @ node_W + node_b) ----------------
__global__ void k_node_proj(const float* __restrict__ x,
                            const float* __restrict__ W,
                            const float* __restrict__ b) {
    int n = blockIdx.x;
    int c = threadIdx.x;
    float acc = b[c];
#pragma unroll
    for (int k = 0; k < 5; k++) acc += x[n * 5 + k] * W[k * HIDD + c];
    d_h[n * HIDD + c] = fmaxf(acc, 0.f);
}

// ---------------- 1: CSR build (dst-grouped, includes self loops) ----------------
__global__ void k_zero() {
    int i = blockIdx.x * blockDim.x + threadIdx.x;
    if (i < NN) d_cnt[i] = 0;
}

__global__ void k_hist(const int* __restrict__ ei) {
    int e = blockIdx.x * blockDim.x + threadIdx.x;
    if (e >= ETOT) return;
    int d = (e < EE) ? ei[EE + e] : (e - EE);
    atomicAdd(&d_cnt[d], 1);
}

__global__ void k_scan() {
    __shared__ int part[1024];
    int t = threadIdx.x;
    const int C = 20;  // 1024*20 >= 20000
    int base = t * C;
    int s = 0;
    for (int i = 0; i < C; i++) {
        int idx = base + i;
        if (idx < NN) s += d_cnt[idx];
    }
    part[t] = s;
    __syncthreads();
    for (int o = 1; o < 1024; o <<= 1) {
        int v = (t >= o) ? part[t - o] : 0;
        __syncthreads();
        part[t] += v;
        __syncthreads();
    }
    int run = part[t] - s;  // exclusive prefix for this chunk
    for (int i = 0; i < C; i++) {
        int idx = base + i;
        if (idx < NN) {
            int c = d_cnt[idx];
            d_off[idx] = run;
            d_cur[idx] = run;
            run += c;
        }
    }
    if (t == 1023) d_off[NN] = part[1023];
}

__global__ void k_scatter(const int* __restrict__ ei) {
    int e = blockIdx.x * blockDim.x + threadIdx.x;
    if (e >= ETOT) return;
    int d, s;
    if (e < EE) { s = ei[e]; d = ei[EE + e]; }
    else        { s = e - EE; d = e - EE; }
    int pos = atomicAdd(&d_cur[d], 1);
    d_csr[pos] = s;
}

// ---------------- 2: z = h @ W  ([20000,128] @ [128,512]) ----------------
__global__ void k_gemm_z(const float* __restrict__ W) {
    __shared__ float As[16][65];
    __shared__ float Bs[16][64];
    int tid = threadIdx.x;               // 256 threads
    int bm = blockIdx.x * 64, bn = blockIdx.y * 64;
    int tx = tid & 15, ty = tid >> 4;
    float acc[4][4] = {};
    int lm = tid >> 2;                   // A-load row 0..63
    int lk = (tid & 3) * 4;              // A-load k offset
    int bkr = tid >> 4;                  // B-load row 0..15
    int bn4 = (tid & 15) * 4;

    for (int k0 = 0; k0 < HIDD; k0 += 16) {
        float4 av = make_float4(0.f, 0.f, 0.f, 0.f);
        if (bm + lm < NN) av = *(const float4*)&d_h[(bm + lm) * HIDD + k0 + lk];
        As[lk + 0][lm] = av.x; As[lk + 1][lm] = av.y;
        As[lk + 2][lm] = av.z; As[lk + 3][lm] = av.w;
        *(float4*)&Bs[bkr][bn4] = *(const float4*)&W[(k0 + bkr) * 512 + bn + bn4];
        __syncthreads();
#pragma unroll
        for (int kk = 0; kk < 16; kk++) {
            float a0 = As[kk][ty * 4 + 0], a1 = As[kk][ty * 4 + 1];
            float a2 = As[kk][ty * 4 + 2], a3 = As[kk][ty * 4 + 3];
            float b0 = Bs[kk][tx * 4 + 0], b1 = Bs[kk][tx * 4 + 1];
            float b2 = Bs[kk][tx * 4 + 2], b3 = Bs[kk][tx * 4 + 3];
            acc[0][0] += a0 * b0; acc[0][1] += a0 * b1; acc[0][2] += a0 * b2; acc[0][3] += a0 * b3;
            acc[1][0] += a1 * b0; acc[1][1] += a1 * b1; acc[1][2] += a1 * b2; acc[1][3] += a1 * b3;
            acc[2][0] += a2 * b0; acc[2][1] += a2 * b1; acc[2][2] += a2 * b2; acc[2][3] += a2 * b3;
            acc[3][0] += a3 * b0; acc[3][1] += a3 * b1; acc[3][2] += a3 * b2; acc[3][3] += a3 * b3;
        }
        __syncthreads();
    }
#pragma unroll
    for (int i = 0; i < 4; i++) {
        int r = bm + ty * 4 + i;
        if (r < NN) {
#pragma unroll
            for (int j = 0; j < 4; j++)
                d_z[r * 512 + bn + tx * 4 + j] = acc[i][j];
        }
    }
}

// ---------------- 3: attention logits e_src/e_dst (warp per node) ----------------
__global__ void k_att(const float* __restrict__ asrc, const float* __restrict__ adst) {
    int wid = threadIdx.x >> 5, lane = threadIdx.x & 31;
    int n = blockIdx.x * 8 + wid;
    if (n >= NN) return;
#pragma unroll
    for (int h = 0; h < HEADS; h++) {
        float4 zv = *(const float4*)&d_z[n * 512 + h * 128 + lane * 4];
        float4 sv = *(const float4*)&asrc[h * 128 + lane * 4];
        float4 dv = *(const float4*)&adst[h * 128 + lane * 4];
        float ss = zv.x * sv.x + zv.y * sv.y + zv.z * sv.z + zv.w * sv.w;
        float sd = zv.x * dv.x + zv.y * dv.y + zv.z * dv.z + zv.w * dv.w;
#pragma unroll
        for (int o = 16; o > 0; o >>= 1) {
            ss += __shfl_xor_sync(0xffffffffu, ss, o);
            sd += __shfl_xor_sync(0xffffffffu, sd, o);
        }
        if (lane == 0) { d_es[n * 4 + h] = ss; d_ed[n * 4 + h] = sd; }
    }
}

// ---------------- 4: fused softmax-aggregate + head-mean + LN + relu + residual ----
__global__ void k_fused(const float* __restrict__ gb,
                        const float* __restrict__ lg,
                        const float* __restrict__ lb) {
    int wid = threadIdx.x >> 5, lane = threadIdx.x & 31;
    int n = blockIdx.x * 8 + wid;
    if (n >= NN) return;

    float4 ed4 = *(const float4*)&d_ed[n * 4];
    float edv[4] = {ed4.x, ed4.y, ed4.z, ed4.w};
    float m[4] = {-1e30f, -1e30f, -1e30f, -1e30f};
    float sden[4] = {0.f, 0.f, 0.f, 0.f};
    float acc[4][4] = {};

    int beg = d_off[n], end = d_off[n + 1];
    for (int e = beg; e < end; e++) {
        int s = d_csr[e];
        float4 es4 = *(const float4*)&d_es[s * 4];
        float ev[4] = {es4.x + edv[0], es4.y + edv[1], es4.z + edv[2], es4.w + edv[3]};
        const float4* zr = (const float4*)&d_z[s * 512];
#pragma unroll
        for (int h = 0; h < HEADS; h++) {
            float e_ = ev[h];
            e_ = (e_ > 0.f) ? e_ : 0.2f * e_;   // leaky_relu 0.2
            float p;
            if (e_ > m[h]) {
                float sc = __expf(m[h] - e_);
                sden[h] *= sc;
                acc[h][0] *= sc; acc[h][1] *= sc; acc[h][2] *= sc; acc[h][3] *= sc;
                m[h] = e_;
                p = 1.f;
            } else {
                p = __expf(e_ - m[h]);
            }
            sden[h] += p;
            float4 zv = zr[h * 32 + lane];
            acc[h][0] += p * zv.x; acc[h][1] += p * zv.y;
            acc[h][2] += p * zv.z; acc[h][3] += p * zv.w;
        }
    }

    // head mean + bias
    float hv[4];
#pragma unroll
    for (int c = 0; c < 4; c++) {
        hv[c] = 0.25f * (acc[0][c] / sden[0] + acc[1][c] / sden[1] +
                         acc[2][c] / sden[2] + acc[3][c] / sden[3]) +
                gb[lane * 4 + c];
    }
    // layernorm over 128 dims
    float s1 = hv[0] + hv[1] + hv[2] + hv[3];
    float s2 = hv[0] * hv[0] + hv[1] * hv[1] + hv[2] * hv[2] + hv[3] * hv[3];
#pragma unroll
    for (int o = 16; o > 0; o >>= 1) {
        s1 += __shfl_xor_sync(0xffffffffu, s1, o);
        s2 += __shfl_xor_sync(0xffffffffu, s2, o);
    }
    float mu = s1 * (1.f / 128.f);
    float var = s2 * (1.f / 128.f) - mu * mu;
    float rstd = rsqrtf(var + 1e-5f);

    float4 hold = *(const float4*)&d_h[n * 128 + lane * 4];
    float ho[4] = {hold.x, hold.y, hold.z, hold.w};
    float outv[4];
#pragma unroll
    for (int c = 0; c < 4; c++) {
        int d = lane * 4 + c;
        float v = (hv[c] - mu) * rstd * lg[d] + lb[d];
        outv[c] = fmaxf(v, 0.f) + ho[c];
    }
    *(float4*)&d_h[n * 128 + lane * 4] = make_float4(outv[0], outv[1], outv[2], outv[3]);
}

// ---------------- 5: P = emb@W1a + b1, Q = emb@W1b ----------------
__global__ void k_pq(const int* __restrict__ odd,
                     const float* __restrict__ sW1,
                     const float* __restrict__ sb1) {
    int i = blockIdx.x, c = threadIdx.x;
    __shared__ float hs[128];
    hs[c] = d_h[odd[i] * 128 + c];
    __syncthreads();
    float p = sb1[c], q = 0.f;
#pragma unroll 8
    for (int k = 0; k < 128; k++) {
        float hk = hs[k];
        p += hk * sW1[k * 128 + c];
        q += hk * sW1[(128 + k) * 128 + c];
    }
    d_P[i * 128 + c] = p;
    d_Q[i * 128 + c] = q;
}

// ---------------- 6: pair scoring (only j>=i blocks; mirror store) ----------------
// Block = 8x8 pairs. GEMM: t[64 pairs][128 k] @ W2[128 k][128 o], then
// score = sum_o relu(.+b2[o]) * w3[o] + b3; write out[i][j] and out[j][i].
__global__ void k_pair(const float* __restrict__ sW2,
                       const float* __restrict__ sb2,
                       const float* __restrict__ sW3,
                       const float* __restrict__ sb3,
                       float* __restrict__ out) {
    int bx = blockIdx.x, by = blockIdx.y;
    if (by < bx) return;   // symmetric: compute upper-triangle blocks only

    __shared__ float As[16][65];     // [kk][pair]
    __shared__ float Bs[16][128];    // [kk][o]
    __shared__ float red[64][17];

    int tid = threadIdx.x;           // 256
    int tx = tid & 15, ty = tid >> 4;
    float acc[4][8] = {};
    int lkk = tid >> 4;              // B-load row
    int lf = tid & 15;

    for (int k0 = 0; k0 < 128; k0 += 16) {
#pragma unroll
        for (int q = 0; q < 4; q++) {
            int v = tid * 4 + q;
            int kk = v >> 6, pp = v & 63;
            int i = bx * 8 + (pp >> 3), j = by * 8 + (pp & 7);
            float t = d_P[i * 128 + k0 + kk] + d_Q[j * 128 + k0 + kk];
            As[kk][pp] = fmaxf(t, 0.f);
        }
        *(float4*)&Bs[lkk][lf * 8]     = *(const float4*)&sW2[(k0 + lkk) * 128 + lf * 8];
        *(float4*)&Bs[lkk][lf * 8 + 4] = *(const float4*)&sW2[(k0 + lkk) * 128 + lf * 8 + 4];
        __syncthreads();
#pragma unroll
        for (int kk = 0; kk < 16; kk++) {
            float a[4], b[8];
#pragma unroll
            for (int p = 0; p < 4; p++) a[p] = As[kk][ty * 4 + p];
#pragma unroll
            for (int o = 0; o < 8; o++) b[o] = Bs[kk][tx * 8 + o];
#pragma unroll
            for (int p = 0; p < 4; p++)
#pragma unroll
                for (int o = 0; o < 8; o++) acc[p][o] += a[p] * b[o];
        }
        __syncthreads();
    }

#pragma unroll
    for (int p = 0; p < 4; p++) {
        float part = 0.f;
#pragma unroll
        for (int c = 0; c < 8; c++) {
            int o = tx * 8 + c;
            part += fmaxf(acc[p][c] + sb2[o], 0.f) * sW3[o];
        }
        red[ty * 4 + p][tx] = part;
    }
    __syncthreads();
    if (tid < 64) {
        float s = sb3[0];
#pragma unroll
        for (int x = 0; x < 16; x++) s += red[tid][x];
        int i = bx * 8 + (tid >> 3), j = by * 8 + (tid & 7);
        if (i < j) {
            out[i * 512 + j] = s;
            out[j * 512 + i] = s;
        } else if (i == j) {
            out[i * 512 + j] = 0.f;
        }
    }
}

// ---------------- launch ----------------
extern "C" void kernel_launch(void* const* d_in, const int* in_sizes, int n_in,
                              void* d_out, int out_size) {
    // Map inputs by element count; stable tie-break follows both the
    // setup_inputs() dict order and the reference() signature order
    // (relative order of equal-sized tensors is identical in both):
    //   1536: att_src, att_dst
    //   384:  gat_b, ln_g, ln_b
    //   128:  node_b, sb1, sb2, sW3   (FOUR tensors — R1 bug: sb2 was skipped)
    const float *x = 0, *node_W = 0, *node_b = 0, *gat_W = 0, *att_src = 0,
                *att_dst = 0, *gat_b = 0, *ln_g = 0, *ln_b = 0, *sW1 = 0,
                *sb1 = 0, *sW2 = 0, *sb2 = 0, *sW3 = 0, *sb3 = 0;
    const int *edge_index = 0, *odd = 0;
    int c1536 = 0, c384 = 0, c128 = 0;
    for (int i = 0; i < n_in; i++) {
        const void* p = d_in[i];
        switch (in_sizes[i]) {
            case 100000: x = (const float*)p; break;
            case 640000: edge_index = (const int*)p; break;
            case 512:    odd = (const int*)p; break;
            case 640:    node_W = (const float*)p; break;
            case 196608: gat_W = (const float*)p; break;
            case 1536:   if (c1536++ == 0) att_src = (const float*)p; else att_dst = (const float*)p; break;
            case 384:    if (c384 == 0) gat_b = (const float*)p;
                         else if (c384 == 1) ln_g = (const float*)p;
                         else ln_b = (const float*)p;
                         c384++; break;
            case 32768:  sW1 = (const float*)p; break;
            case 16384:  sW2 = (const float*)p; break;
            case 128:    if (c128 == 0) node_b = (const float*)p;
                         else if (c128 == 1) sb1 = (const float*)p;
                         else if (c128 == 2) sb2 = (const float*)p;
                         else sW3 = (const float*)p;
                         c128++; break;
            case 1:      sb3 = (const float*)p; break;
            default: break;
        }
    }
    float* outp = (float*)d_out;

    // node projection
    k_node_proj<<<NN, 128>>>(x, node_W, node_b);

    // CSR build (dst-grouped, with self loops)
    k_zero<<<(NN + 255) / 256, 256>>>();
    k_hist<<<(ETOT + 255) / 256, 256>>>(edge_index);
    k_scan<<<1, 1024>>>();
    k_scatter<<<(ETOT + 255) / 256, 256>>>(edge_index);

    // GAT layers
    for (int l = 0; l < NLAYERS; l++) {
        k_gemm_z<<<dim3((NN + 63) / 64, 512 / 64), 256>>>(gat_W + l * HIDD * 512);
        k_att<<<(NN + 7) / 8, 256>>>(att_src + l * 512, att_dst + l * 512);
        k_fused<<<(NN + 7) / 8, 256>>>(gat_b + l * 128, ln_g + l * 128, ln_b + l * 128);
    }

    // pair scoring
    k_pq<<<NODD, 128>>>(odd, sW1, sb1);
    k_pair<<<dim3(64, 64), 256>>>(sW2, sb2, sW3, sb3, outp);
}

// round 3
// speedup vs baseline: 1.5907x; 1.5907x over previous
#include <cuda_runtime.h>
#include <cuda_bf16.h>
#include <cstdint>

#define NN 20000
#define EE 320000
#define ETOT 340000   // EE + NN self loops
#define NODD 512
#define HIDD 128
#define NLAYERS 3
#define SP 136        // padded bf16 smem row stride (conflict-free frag loads)
#define NB 157        // ceil(NN/128)

// ---------------- static scratch ----------------
__device__ float d_h[NN * HIDD];
__device__ float d_z[NN * 512];
__device__ float d_es[NN * 4];
__device__ float d_ed[NN * 4];
__device__ int   d_cnt[NN];
__device__ int   d_cur[NN];
__device__ int   d_off[NN + 1];
__device__ int   d_csr[ETOT];
__device__ int   d_blk[NB + 8];
__device__ float d_P[NODD * HIDD];
__device__ float d_Q[NODD * HIDD];
// split-precision weights/activations (bf16 hi/lo)
__device__ __nv_bfloat16 d_wt_hi[NLAYERS * 512 * 128];   // gat_W transposed [l][n][k]
__device__ __nv_bfloat16 d_wt_lo[NLAYERS * 512 * 128];
__device__ __nv_bfloat16 d_h_hi[NN * 128];
__device__ __nv_bfloat16 d_h_lo[NN * 128];
__device__ __nv_bfloat16 d_w2t_hi[128 * 128];            // sW2 transposed [n][k]
__device__ __nv_bfloat16 d_w2t_lo[128 * 128];

__device__ __forceinline__ void bsplit(float v, __nv_bfloat16& hi, __nv_bfloat16& lo) {
    hi = __float2bfloat16(v);
    lo = __float2bfloat16(v - __bfloat162float(hi));
}

__device__ __forceinline__ void mma_bf16(float* c, uint32_t a0, uint32_t a1, uint32_t a2,
                                         uint32_t a3, uint32_t b0, uint32_t b1) {
    asm volatile(
        "mma.sync.aligned.m16n8k16.row.col.f32.bf16.bf16.f32 "
        "{%0,%1,%2,%3}, {%4,%5,%6,%7}, {%8,%9}, {%0,%1,%2,%3};\n"
        : "+f"(c[0]), "+f"(c[1]), "+f"(c[2]), "+f"(c[3])
        : "r"(a0), "r"(a1), "r"(a2), "r"(a3), "r"(b0), "r"(b1));
}

__device__ __forceinline__ uint32_t ldsm(const __nv_bfloat16* p) {
    return *(const uint32_t*)p;
}

// ---------------- weight prep: gat_W [3][128k][512n] -> [l][n][k] hi/lo ----------------
__global__ void k_prep_w(const float* __restrict__ gw) {
    int l = blockIdx.x >> 9, n = blockIdx.x & 511, k = threadIdx.x;
    float v = gw[(l * 128 + k) * 512 + n];
    __nv_bfloat16 hi, lo; bsplit(v, hi, lo);
    d_wt_hi[(l * 512 + n) * 128 + k] = hi;
    d_wt_lo[(l * 512 + n) * 128 + k] = lo;
}

__global__ void k_prep_w2(const float* __restrict__ w2) {
    int n = blockIdx.x, k = threadIdx.x;
    float v = w2[k * 128 + n];
    __nv_bfloat16 hi, lo; bsplit(v, hi, lo);
    d_w2t_hi[n * 128 + k] = hi;
    d_w2t_lo[n * 128 + k] = lo;
}

__global__ void k_prep_h() {
    int i = blockIdx.x * blockDim.x + threadIdx.x;
    if (i >= NN * 128) return;
    __nv_bfloat16 hi, lo; bsplit(d_h[i], hi, lo);
    d_h_hi[i] = hi; d_h_lo[i] = lo;
}

// ---------------- node projection ----------------
__global__ void k_node_proj(const float* __restrict__ x,
                            const float* __restrict__ W,
                            const float* __restrict__ b) {
    int n = blockIdx.x, c = threadIdx.x;
    float acc = b[c];
#pragma unroll
    for (int k = 0; k < 5; k++) acc += x[n * 5 + k] * W[k * HIDD + c];
    d_h[n * HIDD + c] = fmaxf(acc, 0.f);
}

// ---------------- CSR build ----------------
__global__ void k_zero() {
    int i = blockIdx.x * blockDim.x + threadIdx.x;
    if (i < NN) d_cnt[i] = 0;
}
__global__ void k_hist(const int* __restrict__ ei) {
    int e = blockIdx.x * blockDim.x + threadIdx.x;
    if (e >= ETOT) return;
    int d = (e < EE) ? ei[EE + e] : (e - EE);
    atomicAdd(&d_cnt[d], 1);
}
__global__ void k_blksum() {
    int b = blockIdx.x, t = threadIdx.x, i = b * 128 + t;
    int v = (i < NN) ? d_cnt[i] : 0;
#pragma unroll
    for (int o = 16; o; o >>= 1) v += __shfl_xor_sync(0xffffffffu, v, o);
    __shared__ int ws[4];
    if ((t & 31) == 0) ws[t >> 5] = v;
    __syncthreads();
    if (t == 0) d_blk[b] = ws[0] + ws[1] + ws[2] + ws[3];
}
__global__ void k_blkscan() {   // 160 threads
    int t = threadIdx.x, lane = t & 31, w = t >> 5;
    int v = (t < NB) ? d_blk[t] : 0;
    int x = v;
#pragma unroll
    for (int o = 1; o < 32; o <<= 1) {
        int y = __shfl_up_sync(0xffffffffu, x, o);
        if (lane >= o) x += y;
    }
    __shared__ int ws[5];
    if (lane == 31) ws[w] = x;
    __syncthreads();
    int add = 0;
    for (int q = 0; q < w; q++) add += ws[q];
    if (t < NB) d_blk[t] = x - v + add;   // exclusive block prefix
}
__global__ void k_apply() {
    int b = blockIdx.x, t = threadIdx.x, i = b * 128 + t;
    int lane = t & 31, w = t >> 5;
    int v = (i < NN) ? d_cnt[i] : 0;
    int x = v;
#pragma unroll
    for (int o = 1; o < 32; o <<= 1) {
        int y = __shfl_up_sync(0xffffffffu, x, o);
        if (lane >= o) x += y;
    }
    __shared__ int ws[4];
    if (lane == 31) ws[w] = x;
    __syncthreads();
    int add = 0;
    for (int q = 0; q < w; q++) add += ws[q];
    int ex = x - v + add + d_blk[b];
    if (i < NN) { d_off[i] = ex; d_cur[i] = ex; }
    if (i == 0) d_off[NN] = ETOT;
}
__global__ void k_scatter(const int* __restrict__ ei) {
    int e = blockIdx.x * blockDim.x + threadIdx.x;
    if (e >= ETOT) return;
    int d, s;
    if (e < EE) { s = ei[e]; d = ei[EE + e]; }
    else        { s = e - EE; d = e - EE; }
    int pos = atomicAdd(&d_cur[d], 1);
    d_csr[pos] = s;
}

// ---------------- z = h @ W via bf16x3 mma (block 64x64, warps 2x2, warp 32x32) ----
__global__ void __launch_bounds__(128) k_gemm_z_mma(int l) {
    extern __shared__ __nv_bfloat16 sm[];
    __nv_bfloat16* AH = sm;
    __nv_bfloat16* AL = sm + 64 * SP;
    __nv_bfloat16* WH = sm + 2 * 64 * SP;
    __nv_bfloat16* WL = sm + 3 * 64 * SP;

    int tid = threadIdx.x;
    int bm = blockIdx.x * 64, bn = blockIdx.y * 64;

    // stage A (d_h split) and W slice (pre-split, transposed) into padded smem
#pragma unroll
    for (int i = 0; i < 8; i++) {
        int u = i * 128 + tid;
        int r = u >> 4, kc = (u & 15) * 8;
        uint4 zv = make_uint4(0u, 0u, 0u, 0u);
        uint4 vh = zv, vl = zv;
        if (bm + r < NN) {
            vh = *(const uint4*)&d_h_hi[(bm + r) * 128 + kc];
            vl = *(const uint4*)&d_h_lo[(bm + r) * 128 + kc];
        }
        *(uint4*)&AH[r * SP + kc] = vh;
        *(uint4*)&AL[r * SP + kc] = vl;
        *(uint4*)&WH[r * SP + kc] = *(const uint4*)&d_wt_hi[(l * 512 + bn + r) * 128 + kc];
        *(uint4*)&WL[r * SP + kc] = *(const uint4*)&d_wt_lo[(l * 512 + bn + r) * 128 + kc];
    }
    __syncthreads();

    int wid = tid >> 5, lane = tid & 31;
    int g = lane >> 2, tig = lane & 3;
    int wm = (wid & 1) * 32, wn = (wid >> 1) * 32;

    float c[2][4][4] = {};
#pragma unroll
    for (int ks = 0; ks < 8; ks++) {
        int ko = ks * 16 + 2 * tig;
        uint32_t aH[2][4], aL[2][4];
#pragma unroll
        for (int mt = 0; mt < 2; mt++) {
            int r = wm + mt * 16 + g;
            aH[mt][0] = ldsm(&AH[r * SP + ko]);
            aH[mt][1] = ldsm(&AH[(r + 8) * SP + ko]);
            aH[mt][2] = ldsm(&AH[r * SP + ko + 8]);
            aH[mt][3] = ldsm(&AH[(r + 8) * SP + ko + 8]);
            aL[mt][0] = ldsm(&AL[r * SP + ko]);
            aL[mt][1] = ldsm(&AL[(r + 8) * SP + ko]);
            aL[mt][2] = ldsm(&AL[r * SP + ko + 8]);
            aL[mt][3] = ldsm(&AL[(r + 8) * SP + ko + 8]);
        }
#pragma unroll
        for (int nt = 0; nt < 4; nt++) {
            int col = wn + nt * 8 + g;
            uint32_t bH0 = ldsm(&WH[col * SP + ko]);
            uint32_t bH1 = ldsm(&WH[col * SP + ko + 8]);
            uint32_t bL0 = ldsm(&WL[col * SP + ko]);
            uint32_t bL1 = ldsm(&WL[col * SP + ko + 8]);
#pragma unroll
            for (int mt = 0; mt < 2; mt++) {
                mma_bf16(c[mt][nt], aH[mt][0], aH[mt][1], aH[mt][2], aH[mt][3], bH0, bH1);
                mma_bf16(c[mt][nt], aH[mt][0], aH[mt][1], aH[mt][2], aH[mt][3], bL0, bL1);
                mma_bf16(c[mt][nt], aL[mt][0], aL[mt][1], aL[mt][2], aL[mt][3], bH0, bH1);
            }
        }
    }

#pragma unroll
    for (int mt = 0; mt < 2; mt++) {
        int r0 = bm + wm + mt * 16 + g;
#pragma unroll
        for (int nt = 0; nt < 4; nt++) {
            int col = bn + wn + nt * 8 + 2 * tig;
            if (r0 < NN)     *(float2*)&d_z[r0 * 512 + col]       = make_float2(c[mt][nt][0], c[mt][nt][1]);
            if (r0 + 8 < NN) *(float2*)&d_z[(r0 + 8) * 512 + col] = make_float2(c[mt][nt][2], c[mt][nt][3]);
        }
    }
}

// ---------------- attention logits ----------------
__global__ void k_att(const float* __restrict__ asrc, const float* __restrict__ adst) {
    int wid = threadIdx.x >> 5, lane = threadIdx.x & 31;
    int n = blockIdx.x * 8 + wid;
    if (n >= NN) return;
#pragma unroll
    for (int h = 0; h < 4; h++) {
        float4 zv = *(const float4*)&d_z[n * 512 + h * 128 + lane * 4];
        float4 sv = *(const float4*)&asrc[h * 128 + lane * 4];
        float4 dv = *(const float4*)&adst[h * 128 + lane * 4];
        float ss = zv.x * sv.x + zv.y * sv.y + zv.z * sv.z + zv.w * sv.w;
        float sd = zv.x * dv.x + zv.y * dv.y + zv.z * dv.z + zv.w * dv.w;
#pragma unroll
        for (int o = 16; o > 0; o >>= 1) {
            ss += __shfl_xor_sync(0xffffffffu, ss, o);
            sd += __shfl_xor_sync(0xffffffffu, sd, o);
        }
        if (lane == 0) { d_es[n * 4 + h] = ss; d_ed[n * 4 + h] = sd; }
    }
}

// ---------------- fused softmax-aggregate + head-mean + LN + relu + residual ----
__global__ void k_fused(const float* __restrict__ gb,
                        const float* __restrict__ lg,
                        const float* __restrict__ lb) {
    int wid = threadIdx.x >> 5, lane = threadIdx.x & 31;
    int n = blockIdx.x * 8 + wid;
    if (n >= NN) return;

    float4 ed4 = *(const float4*)&d_ed[n * 4];
    float edv[4] = {ed4.x, ed4.y, ed4.z, ed4.w};
    float m[4] = {-1e30f, -1e30f, -1e30f, -1e30f};
    float sden[4] = {0.f, 0.f, 0.f, 0.f};
    float acc[4][4] = {};

    int beg = d_off[n], end = d_off[n + 1];
    for (int e = beg; e < end; e++) {
        int s = d_csr[e];
        float4 es4 = *(const float4*)&d_es[s * 4];
        float ev[4] = {es4.x + edv[0], es4.y + edv[1], es4.z + edv[2], es4.w + edv[3]};
        const float4* zr = (const float4*)&d_z[s * 512];
#pragma unroll
        for (int h = 0; h < 4; h++) {
            float e_ = ev[h];
            e_ = (e_ > 0.f) ? e_ : 0.2f * e_;
            float p;
            if (e_ > m[h]) {
                float sc = __expf(m[h] - e_);
                sden[h] *= sc;
                acc[h][0] *= sc; acc[h][1] *= sc; acc[h][2] *= sc; acc[h][3] *= sc;
                m[h] = e_;
                p = 1.f;
            } else {
                p = __expf(e_ - m[h]);
            }
            sden[h] += p;
            float4 zv = zr[h * 32 + lane];
            acc[h][0] += p * zv.x; acc[h][1] += p * zv.y;
            acc[h][2] += p * zv.z; acc[h][3] += p * zv.w;
        }
    }

    float hv[4];
#pragma unroll
    for (int c = 0; c < 4; c++) {
        hv[c] = 0.25f * (acc[0][c] / sden[0] + acc[1][c] / sden[1] +
                         acc[2][c] / sden[2] + acc[3][c] / sden[3]) +
                gb[lane * 4 + c];
    }
    float s1 = hv[0] + hv[1] + hv[2] + hv[3];
    float s2 = hv[0] * hv[0] + hv[1] * hv[1] + hv[2] * hv[2] + hv[3] * hv[3];
#pragma unroll
    for (int o = 16; o > 0; o >>= 1) {
        s1 += __shfl_xor_sync(0xffffffffu, s1, o);
        s2 += __shfl_xor_sync(0xffffffffu, s2, o);
    }
    float mu = s1 * (1.f / 128.f);
    float var = s2 * (1.f / 128.f) - mu * mu;
    float rstd = rsqrtf(var + 1e-5f);

    float4 hold = *(const float4*)&d_h[n * 128 + lane * 4];
    float ho[4] = {hold.x, hold.y, hold.z, hold.w};
    float outv[4];
#pragma unroll
    for (int c = 0; c < 4; c++) {
        int d = lane * 4 + c;
        float v = (hv[c] - mu) * rstd * lg[d] + lb[d];
        outv[c] = fmaxf(v, 0.f) + ho[c];
    }
    *(float4*)&d_h[n * 128 + lane * 4] = make_float4(outv[0], outv[1], outv[2], outv[3]);
}

// ---------------- P/Q for pair MLP layer 1 ----------------
__global__ void k_pq(const int* __restrict__ odd,
                     const float* __restrict__ sW1,
                     const float* __restrict__ sb1) {
    int i = blockIdx.x, c = threadIdx.x;
    __shared__ float hs[128];
    hs[c] = d_h[odd[i] * 128 + c];
    __syncthreads();
    float p = sb1[c], q = 0.f;
#pragma unroll 8
    for (int k = 0; k < 128; k++) {
        float hk = hs[k];
        p += hk * sW1[k * 128 + c];
        q += hk * sW1[(128 + k) * 128 + c];
    }
    d_P[i * 128 + c] = p;
    d_Q[i * 128 + c] = q;
}

// ---------------- pair scoring: bf16x3 mma, block 64 pairs x 128 out ----------------
__global__ void __launch_bounds__(128) k_pair_mma(const float* __restrict__ sb2,
                                                  const float* __restrict__ sW3,
                                                  const float* __restrict__ sb3,
                                                  float* __restrict__ out) {
    int bx = blockIdx.x, by = blockIdx.y;
    if (by < bx) return;

    extern __shared__ __nv_bfloat16 sm[];
    __nv_bfloat16* AH = sm;                       // 64 x SP
    __nv_bfloat16* AL = sm + 64 * SP;
    __nv_bfloat16* WH = sm + 2 * 64 * SP;         // 128 x SP
    __nv_bfloat16* WL = sm + 2 * 64 * SP + 128 * SP;

    int tid = threadIdx.x;

    // stage W2t (pre-split, transposed)
#pragma unroll
    for (int i = 0; i < 16; i++) {
        int u = i * 128 + tid;
        int n = u >> 4, kc = (u & 15) * 8;
        *(uint4*)&WH[n * SP + kc] = *(const uint4*)&d_w2t_hi[n * 128 + kc];
        *(uint4*)&WL[n * SP + kc] = *(const uint4*)&d_w2t_lo[n * 128 + kc];
    }
    // build A = relu(P[i] + Q[j]) split
#pragma unroll
    for (int p = 0; p < 64; p++) {
        int ii = bx * 8 + (p >> 3), jj = by * 8 + (p & 7);
        float v = fmaxf(d_P[ii * 128 + tid] + d_Q[jj * 128 + tid], 0.f);
        __nv_bfloat16 hi, lo; bsplit(v, hi, lo);
        AH[p * SP + tid] = hi;
        AL[p * SP + tid] = lo;
    }
    __syncthreads();

    int wid = tid >> 5, lane = tid & 31;
    int g = lane >> 2, tig = lane & 3;
    int wm = (wid & 1) * 32, wn = (wid >> 1) * 64;

    float c[2][8][4] = {};
#pragma unroll
    for (int ks = 0; ks < 8; ks++) {
        int ko = ks * 16 + 2 * tig;
        uint32_t aH[2][4], aL[2][4];
#pragma unroll
        for (int mt = 0; mt < 2; mt++) {
            int r = wm + mt * 16 + g;
            aH[mt][0] = ldsm(&AH[r * SP + ko]);
            aH[mt][1] = ldsm(&AH[(r + 8) * SP + ko]);
            aH[mt][2] = ldsm(&AH[r * SP + ko + 8]);
            aH[mt][3] = ldsm(&AH[(r + 8) * SP + ko + 8]);
            aL[mt][0] = ldsm(&AL[r * SP + ko]);
            aL[mt][1] = ldsm(&AL[(r + 8) * SP + ko]);
            aL[mt][2] = ldsm(&AL[r * SP + ko + 8]);
            aL[mt][3] = ldsm(&AL[(r + 8) * SP + ko + 8]);
        }
#pragma unroll
        for (int nt = 0; nt < 8; nt++) {
            int col = wn + nt * 8 + g;
            uint32_t bH0 = ldsm(&WH[col * SP + ko]);
            uint32_t bH1 = ldsm(&WH[col * SP + ko + 8]);
            uint32_t bL0 = ldsm(&WL[col * SP + ko]);
            uint32_t bL1 = ldsm(&WL[col * SP + ko + 8]);
#pragma unroll
            for (int mt = 0; mt < 2; mt++) {
                mma_bf16(c[mt][nt], aH[mt][0], aH[mt][1], aH[mt][2], aH[mt][3], bH0, bH1);
                mma_bf16(c[mt][nt], aH[mt][0], aH[mt][1], aH[mt][2], aH[mt][3], bL0, bL1);
                mma_bf16(c[mt][nt], aL[mt][0], aL[mt][1], aL[mt][2], aL[mt][3], bH0, bH1);
            }
        }
    }
    __syncthreads();   // smem free -> reuse for reduction

    float* red = (float*)sm;   // [64 rows][2 col-halves]
#pragma unroll
    for (int mt = 0; mt < 2; mt++) {
        float p0 = 0.f, p1 = 0.f;
#pragma unroll
        for (int nt = 0; nt < 8; nt++) {
            int c0 = wn + nt * 8 + 2 * tig;
            float w30 = sW3[c0], w31 = sW3[c0 + 1];
            float bb0 = sb2[c0], bb1 = sb2[c0 + 1];
            p0 += fmaxf(c[mt][nt][0] + bb0, 0.f) * w30 + fmaxf(c[mt][nt][1] + bb1, 0.f) * w31;
            p1 += fmaxf(c[mt][nt][2] + bb0, 0.f) * w30 + fmaxf(c[mt][nt][3] + bb1, 0.f) * w31;
        }
#pragma unroll
        for (int o = 1; o < 4; o <<= 1) {
            p0 += __shfl_xor_sync(0xffffffffu, p0, o);
            p1 += __shfl_xor_sync(0xffffffffu, p1, o);
        }
        if (tig == 0) {
            int r = wm + mt * 16 + g;
            red[r * 2 + (wid >> 1)] = p0;
            red[(r + 8) * 2 + (wid >> 1)] = p1;
        }
    }
    __syncthreads();
    if (tid < 64) {
        float s = red[tid * 2] + red[tid * 2 + 1] + sb3[0];
        int i = bx * 8 + (tid >> 3), j = by * 8 + (tid & 7);
        if (i < j) {
            out[i * 512 + j] = s;
            out[j * 512 + i] = s;
        } else if (i == j) {
            out[i * 512 + j] = 0.f;
        }
    }
}

// ---------------- launch ----------------
extern "C" void kernel_launch(void* const* d_in, const int* in_sizes, int n_in,
                              void* d_out, int out_size) {
    const float *x = 0, *node_W = 0, *node_b = 0, *gat_W = 0, *att_src = 0,
                *att_dst = 0, *gat_b = 0, *ln_g = 0, *ln_b = 0, *sW1 = 0,
                *sb1 = 0, *sW2 = 0, *sb2 = 0, *sW3 = 0, *sb3 = 0;
    const int *edge_index = 0, *odd = 0;
    int c1536 = 0, c384 = 0, c128 = 0;
    for (int i = 0; i < n_in; i++) {
        const void* p = d_in[i];
        switch (in_sizes[i]) {
            case 100000: x = (const float*)p; break;
            case 640000: edge_index = (const int*)p; break;
            case 512:    odd = (const int*)p; break;
            case 640:    node_W = (const float*)p; break;
            case 196608: gat_W = (const float*)p; break;
            case 1536:   if (c1536++ == 0) att_src = (const float*)p; else att_dst = (const float*)p; break;
            case 384:    if (c384 == 0) gat_b = (const float*)p;
                         else if (c384 == 1) ln_g = (const float*)p;
                         else ln_b = (const float*)p;
                         c384++; break;
            case 32768:  sW1 = (const float*)p; break;
            case 16384:  sW2 = (const float*)p; break;
            case 128:    if (c128 == 0) node_b = (const float*)p;
                         else if (c128 == 1) sb1 = (const float*)p;
                         else if (c128 == 2) sb2 = (const float*)p;
                         else sW3 = (const float*)p;
                         c128++; break;
            case 1:      sb3 = (const float*)p; break;
            default: break;
        }
    }
    float* outp = (float*)d_out;

    const int GEMM_SMEM = 4 * 64 * SP * 2;                 // 69632 B
    const int PAIR_SMEM = (2 * 64 + 2 * 128) * SP * 2;     // 104448 B
    cudaFuncSetAttribute(k_gemm_z_mma, cudaFuncAttributeMaxDynamicSharedMemorySize, GEMM_SMEM);
    cudaFuncSetAttribute(k_pair_mma, cudaFuncAttributeMaxDynamicSharedMemorySize, PAIR_SMEM);

    // launch 0..4, so launch #5 (ncu -s 5 -c 1) is k_gemm_z_mma
    k_prep_w<<<NLAYERS * 512, 128>>>(gat_W);                       // 0
    k_node_proj<<<NN, 128>>>(x, node_W, node_b);                   // 1
    k_zero<<<(NN + 255) / 256, 256>>>();                           // 2
    k_hist<<<(ETOT + 255) / 256, 256>>>(edge_index);               // 3
    k_prep_h<<<(NN * 128 + 255) / 256, 256>>>();                   // 4
    k_gemm_z_mma<<<dim3(313, 8), 128, GEMM_SMEM>>>(0);             // 5 <- profiled
    k_blksum<<<NB, 128>>>();
    k_blkscan<<<1, 160>>>();
    k_apply<<<NB, 128>>>();
    k_scatter<<<(ETOT + 255) / 256, 256>>>(edge_index);
    k_att<<<(NN + 7) / 8, 256>>>(att_src, att_dst);
    k_fused<<<(NN + 7) / 8, 256>>>(gat_b, ln_g, ln_b);

    for (int l = 1; l < NLAYERS; l++) {
        k_prep_h<<<(NN * 128 + 255) / 256, 256>>>();
        k_gemm_z_mma<<<dim3(313, 8), 128, GEMM_SMEM>>>(l);
        k_att<<<(NN + 7) / 8, 256>>>(att_src + l * 512, att_dst + l * 512);
        k_fused<<<(NN + 7) / 8, 256>>>(gat_b + l * 128, ln_g + l * 128, ln_b + l * 128);
    }

    k_prep_w2<<<128, 128>>>(sW2);
    k_pq<<<NODD, 128>>>(odd, sW1, sb1);
    k_pair_mma<<<dim3(64, 64), 128, PAIR_SMEM>>>(sb2, sW3, sb3, outp);
}